// round 1
// baseline (speedup 1.0000x reference)
#include <cuda_runtime.h>

// Problem constants (from reference): B=8192, T=64, D=512
#define BB 8192
#define TT 64
#define DD 512

__device__ __forceinline__ float warp_reduce_sum(float v) {
    #pragma unroll
    for (int off = 16; off > 0; off >>= 1)
        v += __shfl_xor_sync(0xFFFFFFFFu, v, off);
    return v;
}

__global__ __launch_bounds__(256, 8)
void sdpa_decode_kernel(const float* __restrict__ q,
                        const float* __restrict__ k,
                        const float* __restrict__ v,
                        const int*   __restrict__ pad_mask,
                        float* __restrict__ out,       // [B, D]
                        float* __restrict__ attn_out)  // [B, T]
{
    const int b    = blockIdx.x;
    const int tid  = threadIdx.x;
    const int warp = tid >> 5;
    const int lane = tid & 31;

    const float INV_TEMP = 0.04419417382415922f;   // 1/sqrt(512)
    const float MASK_FILL = -1000.0f;

    __shared__ float4 qs[DD / 4];     // q row, 512 floats as 128 float4
    __shared__ float  s_logit[TT];    // logits then probabilities

    // ---- load q[b] into shared (float4, coalesced) ----
    const float4* q4 = reinterpret_cast<const float4*>(q + (size_t)b * DD);
    if (tid < DD / 4) qs[tid] = q4[tid];
    __syncthreads();

    // ---- QK^T: 8 warps, each warp computes 8 of the 64 dot products ----
    const float4* kbase = reinterpret_cast<const float4*>(k + (size_t)b * TT * DD);
    #pragma unroll
    for (int ti = 0; ti < TT / 8; ti++) {
        const int t = warp + ti * 8;
        const float4* krow = kbase + (size_t)t * (DD / 4);
        float partial = 0.0f;
        #pragma unroll
        for (int j = 0; j < 4; j++) {
            const int idx = lane + j * 32;          // 0..127 float4s
            float4 kv4 = krow[idx];
            float4 qv4 = qs[idx];
            partial += kv4.x * qv4.x + kv4.y * qv4.y + kv4.z * qv4.z + kv4.w * qv4.w;
        }
        partial = warp_reduce_sum(partial);
        if (lane == 0) s_logit[t] = partial;
    }
    __syncthreads();

    // ---- masked softmax over T=64, done by warp 0 (2 values per lane) ----
    if (warp == 0) {
        const int* mrow = pad_mask + (size_t)b * TT;
        float v0 = s_logit[lane]      * INV_TEMP;
        float v1 = s_logit[lane + 32] * INV_TEMP;
        if (mrow[lane])      v0 = MASK_FILL;
        if (mrow[lane + 32]) v1 = MASK_FILL;

        // max-reduce
        float m = fmaxf(v0, v1);
        #pragma unroll
        for (int off = 16; off > 0; off >>= 1)
            m = fmaxf(m, __shfl_xor_sync(0xFFFFFFFFu, m, off));

        float e0 = __expf(v0 - m);
        float e1 = __expf(v1 - m);
        float ssum = warp_reduce_sum(e0 + e1);
        float inv = 1.0f / ssum;
        float p0 = e0 * inv;
        float p1 = e1 * inv;
        s_logit[lane]      = p0;
        s_logit[lane + 32] = p1;
        // write attention probabilities output
        attn_out[(size_t)b * TT + lane]      = p0;
        attn_out[(size_t)b * TT + lane + 32] = p1;
    }
    __syncthreads();

    // ---- P·V: each of 256 threads owns 2 output dims (float2, coalesced) ----
    const float2* vbase = reinterpret_cast<const float2*>(v + (size_t)b * TT * DD);
    const int d2 = tid;                        // float2 index 0..255
    float2 acc = make_float2(0.0f, 0.0f);
    #pragma unroll 8
    for (int t = 0; t < TT; t++) {
        float  p  = s_logit[t];
        float2 vv = vbase[(size_t)t * (DD / 2) + d2];
        acc.x += p * vv.x;
        acc.y += p * vv.y;
    }
    reinterpret_cast<float2*>(out + (size_t)b * DD)[d2] = acc;
}

extern "C" void kernel_launch(void* const* d_in, const int* in_sizes, int n_in,
                              void* d_out, int out_size) {
    const float* q        = (const float*)d_in[0];   // [B, D]
    const float* k        = (const float*)d_in[1];   // [B, T, D]
    const float* v        = (const float*)d_in[2];   // [B, T, D]
    const int*   pad_mask = (const int*)  d_in[3];   // [B, T]

    float* out      = (float*)d_out;                 // [B,1,D] flattened first
    float* attn_out = (float*)d_out + (size_t)BB * DD; // [B,1,T] second

    sdpa_decode_kernel<<<BB, 256>>>(q, k, v, pad_mask, out, attn_out);
}

// round 2
// speedup vs baseline: 1.7985x; 1.7985x over previous
#include <cuda_runtime.h>

// Problem constants: B=8192, T=64, D=512
#define BB 8192
#define TT 64
#define DD 512

__device__ __forceinline__ float warp_reduce_sum(float v) {
    #pragma unroll
    for (int off = 16; off > 0; off >>= 1)
        v += __shfl_xor_sync(0xFFFFFFFFu, v, off);
    return v;
}

__global__ __launch_bounds__(256, 8)
void sdpa_decode_kernel(const float* __restrict__ q,
                        const float* __restrict__ k,
                        const float* __restrict__ v,
                        const int*   __restrict__ pad_mask,
                        float* __restrict__ out,       // [B, D]
                        float* __restrict__ attn_out)  // [B, T]
{
    const int b    = blockIdx.x;
    const int tid  = threadIdx.x;
    const int warp = tid >> 5;
    const int lane = tid & 31;

    const float INV_TEMP  = 0.04419417382415922f;   // 1/sqrt(512)
    const float MASK_FILL = -1000.0f;

    __shared__ float4 qs[DD / 4];     // q row: 512 floats = 128 float4
    __shared__ float  s_logit[TT];    // raw q·k dots (unmasked slots)
    __shared__ int    s_mask[TT];
    __shared__ float  s_p[TT];        // compacted probabilities
    __shared__ int    s_t[TT];        // compacted t indices
    __shared__ int    s_n;            // active count

    // ---- load q[b] and pad_mask[b] into shared ----
    const float4* q4 = reinterpret_cast<const float4*>(q + (size_t)b * DD);
    if (tid < DD / 4) qs[tid] = q4[tid];
    if (tid < TT)     s_mask[tid] = pad_mask[(size_t)b * TT + tid];
    __syncthreads();

    // ---- QK^T: 8 warps × 8 rows each; SKIP masked rows entirely ----
    const float4* kbase = reinterpret_cast<const float4*>(k + (size_t)b * TT * DD);
    #pragma unroll
    for (int ti = 0; ti < TT / 8; ti++) {
        const int t = warp + ti * 8;
        if (s_mask[t]) {
            if (lane == 0) s_logit[t] = 0.0f;   // placeholder, never used
            continue;
        }
        const float4* krow = kbase + (size_t)t * (DD / 4);
        float partial = 0.0f;
        #pragma unroll
        for (int j = 0; j < 4; j++) {
            const int idx = lane + j * 32;      // 0..127 float4s
            float4 kv4 = krow[idx];
            float4 qv4 = qs[idx];
            partial += kv4.x * qv4.x + kv4.y * qv4.y + kv4.z * qv4.z + kv4.w * qv4.w;
        }
        partial = warp_reduce_sum(partial);
        if (lane == 0) s_logit[t] = partial;
    }
    __syncthreads();

    // ---- masked softmax (warp 0, 2 values/lane) + ballot compaction ----
    if (warp == 0) {
        float v0 = s_mask[lane]      ? MASK_FILL : s_logit[lane]      * INV_TEMP;
        float v1 = s_mask[lane + 32] ? MASK_FILL : s_logit[lane + 32] * INV_TEMP;

        float m = fmaxf(v0, v1);
        #pragma unroll
        for (int off = 16; off > 0; off >>= 1)
            m = fmaxf(m, __shfl_xor_sync(0xFFFFFFFFu, m, off));

        float e0 = __expf(v0 - m);   // underflows to exact 0 for masked (matches ref)
        float e1 = __expf(v1 - m);
        float ssum = warp_reduce_sum(e0 + e1);
        float inv = 1.0f / ssum;
        float p0 = e0 * inv;
        float p1 = e1 * inv;

        attn_out[(size_t)b * TT + lane]      = p0;
        attn_out[(size_t)b * TT + lane + 32] = p1;

        // compact nonzero-probability rows (handles all-masked edge case too)
        bool a0 = (p0 != 0.0f);
        bool a1 = (p1 != 0.0f);
        unsigned b0 = __ballot_sync(0xFFFFFFFFu, a0);
        unsigned b1 = __ballot_sync(0xFFFFFFFFu, a1);
        int n0 = __popc(b0);
        unsigned lt = (1u << lane) - 1u;
        if (a0) { int pos = __popc(b0 & lt);       s_t[pos] = lane;      s_p[pos] = p0; }
        if (a1) { int pos = n0 + __popc(b1 & lt);  s_t[pos] = lane + 32; s_p[pos] = p1; }
        if (lane == 0) s_n = n0 + __popc(b1);
    }
    __syncthreads();

    // ---- P·V over ACTIVE rows only; 256 threads × float2, unroll×4 for MLP ----
    const float2* vbase = reinterpret_cast<const float2*>(v + (size_t)b * TT * DD);
    const int d2 = tid;                 // float2 index 0..255
    const int n  = s_n;
    float2 acc = make_float2(0.0f, 0.0f);

    int i = 0;
    for (; i + 4 <= n; i += 4) {
        float pa = s_p[i],     pb = s_p[i + 1], pc = s_p[i + 2], pd = s_p[i + 3];
        int   ta = s_t[i],     tb = s_t[i + 1], tc = s_t[i + 2], td = s_t[i + 3];
        float2 va = vbase[(size_t)ta * (DD / 2) + d2];
        float2 vb = vbase[(size_t)tb * (DD / 2) + d2];
        float2 vc = vbase[(size_t)tc * (DD / 2) + d2];
        float2 vd = vbase[(size_t)td * (DD / 2) + d2];
        acc.x += pa * va.x; acc.y += pa * va.y;
        acc.x += pb * vb.x; acc.y += pb * vb.y;
        acc.x += pc * vc.x; acc.y += pc * vc.y;
        acc.x += pd * vd.x; acc.y += pd * vd.y;
    }
    for (; i < n; i++) {
        float  p  = s_p[i];
        float2 vv = vbase[(size_t)s_t[i] * (DD / 2) + d2];
        acc.x += p * vv.x; acc.y += p * vv.y;
    }
    reinterpret_cast<float2*>(out + (size_t)b * DD)[d2] = acc;
}

extern "C" void kernel_launch(void* const* d_in, const int* in_sizes, int n_in,
                              void* d_out, int out_size) {
    const float* q        = (const float*)d_in[0];   // [B, D]
    const float* k        = (const float*)d_in[1];   // [B, T, D]
    const float* v        = (const float*)d_in[2];   // [B, T, D]
    const int*   pad_mask = (const int*)  d_in[3];   // [B, T]

    float* out      = (float*)d_out;                   // [B,1,D]
    float* attn_out = (float*)d_out + (size_t)BB * DD; // [B,1,T]

    sdpa_decode_kernel<<<BB, 256>>>(q, k, v, pad_mask, out, attn_out);
}